// round 2
// baseline (speedup 1.0000x reference)
#include <cuda_runtime.h>

#define N_NODES_MAX 50000
#define N_EDGES_MAX 800000
#define IN_CH 64
#define HIDDEN 16
#define OUT_CH 8

// Scratch (allocation-free rule: __device__ globals)
__device__ float g_deg[N_NODES_MAX];
__device__ float g_p1[N_NODES_MAX * HIDDEN];
__device__ float g_r1[N_NODES_MAX * HIDDEN];
__device__ float g_s1[N_NODES_MAX * HIDDEN];
__device__ float g_h [N_NODES_MAX * HIDDEN];
__device__ float g_p2[N_NODES_MAX * OUT_CH];
__device__ float g_r2[N_NODES_MAX * OUT_CH];
__device__ float g_s2[N_NODES_MAX * OUT_CH];
__device__ int   g_src[N_EDGES_MAX];
__device__ int   g_dst[N_EDGES_MAX];
__device__ int   g_is64;

// Detect whether edge_index is int64 or int32.
// int64 little-endian with values in [0, 50000): every odd int32 word of the
// first row is 0. int32: odd words are random edge indices — all-zero over
// 512 samples is impossible.
__global__ void detect_kernel(const int* __restrict__ ei_raw, int n_words) {
    if (threadIdx.x == 0 && blockIdx.x == 0) {
        int nz = 0;
        int lim = n_words < 1024 ? n_words : 1024;
        for (int i = 1; i < lim; i += 2) nz += (ei_raw[i] != 0);
        g_is64 = (nz == 0) ? 1 : 0;
    }
}

// Expand edge_index into int32 src/dst arrays for either dtype.
__global__ void decode_kernel(const int* __restrict__ ei_raw, int n_edges) {
    int e = blockIdx.x * blockDim.x + threadIdx.x;
    if (e >= n_edges) return;
    if (g_is64) {
        g_src[e] = ei_raw[2 * e];                  // low word of int64 src
        g_dst[e] = ei_raw[2 * n_edges + 2 * e];    // low word of int64 dst
    } else {
        g_src[e] = ei_raw[e];
        g_dst[e] = ei_raw[n_edges + e];
    }
}

__global__ void zero_kernel(int n_nodes) {
    int i = blockIdx.x * blockDim.x + threadIdx.x;
    int nh = n_nodes * HIDDEN;
    int no = n_nodes * OUT_CH;
    if (i < n_nodes) g_deg[i] = 0.0f;
    if (i < nh)      g_s1[i]  = 0.0f;
    if (i < no)      g_s2[i]  = 0.0f;
}

// p1 = x @ W1l^T ; r1 = x @ W1r^T + b1   (one thread per node)
__global__ void gemm1_kernel(const float* __restrict__ x,
                             const float* __restrict__ W1l,
                             const float* __restrict__ W1r,
                             const float* __restrict__ b1,
                             int n_nodes) {
    __shared__ float sWl[HIDDEN * IN_CH];
    __shared__ float sWr[HIDDEN * IN_CH];
    __shared__ float sb[HIDDEN];
    for (int i = threadIdx.x; i < HIDDEN * IN_CH; i += blockDim.x) {
        sWl[i] = W1l[i];
        sWr[i] = W1r[i];
    }
    if (threadIdx.x < HIDDEN) sb[threadIdx.x] = b1[threadIdx.x];
    __syncthreads();

    int n = blockIdx.x * blockDim.x + threadIdx.x;
    if (n >= n_nodes) return;

    float accl[HIDDEN], accr[HIDDEN];
#pragma unroll
    for (int h = 0; h < HIDDEN; h++) { accl[h] = 0.0f; accr[h] = sb[h]; }

    const float4* xr = reinterpret_cast<const float4*>(x + (size_t)n * IN_CH);
#pragma unroll
    for (int c4 = 0; c4 < IN_CH / 4; c4++) {
        float4 v = xr[c4];
#pragma unroll
        for (int h = 0; h < HIDDEN; h++) {
            const float* wl = &sWl[h * IN_CH + c4 * 4];
            const float* wr = &sWr[h * IN_CH + c4 * 4];
            accl[h] += v.x * wl[0] + v.y * wl[1] + v.z * wl[2] + v.w * wl[3];
            accr[h] += v.x * wr[0] + v.y * wr[1] + v.z * wr[2] + v.w * wr[3];
        }
    }
#pragma unroll
    for (int h = 0; h < HIDDEN; h++) {
        g_p1[n * HIDDEN + h] = accl[h];
        g_r1[n * HIDDEN + h] = accr[h];
    }
}

// Per edge: deg[dst]+=1 ; s1[dst] += p1[src]  (16 floats)
__global__ void scatter1_kernel(int n_edges, int n_nodes) {
    int e = blockIdx.x * blockDim.x + threadIdx.x;
    if (e >= n_edges) return;
    unsigned src = (unsigned)g_src[e];
    unsigned dst = (unsigned)g_dst[e];
    if (src >= (unsigned)n_nodes || dst >= (unsigned)n_nodes) return;
    atomicAdd(&g_deg[dst], 1.0f);
    const float4* p = reinterpret_cast<const float4*>(&g_p1[src * HIDDEN]);
    float* s = &g_s1[dst * HIDDEN];
#pragma unroll
    for (int q = 0; q < HIDDEN / 4; q++) {
        float4 v = p[q];
        atomicAdd(&s[q * 4 + 0], v.x);
        atomicAdd(&s[q * 4 + 1], v.y);
        atomicAdd(&s[q * 4 + 2], v.z);
        atomicAdd(&s[q * 4 + 3], v.w);
    }
}

// h = relu(s1 / max(deg,1) + r1)
__global__ void combine1_kernel(int n_nodes) {
    int i = blockIdx.x * blockDim.x + threadIdx.x;
    if (i >= n_nodes * HIDDEN) return;
    float d = fmaxf(g_deg[i / HIDDEN], 1.0f);
    float v = g_s1[i] / d + g_r1[i];
    g_h[i] = fmaxf(v, 0.0f);
}

// p2 = h @ W2l^T ; r2 = h @ W2r^T + b2
__global__ void gemm2_kernel(const float* __restrict__ W2l,
                             const float* __restrict__ W2r,
                             const float* __restrict__ b2,
                             int n_nodes) {
    __shared__ float sWl[OUT_CH * HIDDEN];
    __shared__ float sWr[OUT_CH * HIDDEN];
    __shared__ float sb[OUT_CH];
    for (int i = threadIdx.x; i < OUT_CH * HIDDEN; i += blockDim.x) {
        sWl[i] = W2l[i];
        sWr[i] = W2r[i];
    }
    if (threadIdx.x < OUT_CH) sb[threadIdx.x] = b2[threadIdx.x];
    __syncthreads();

    int n = blockIdx.x * blockDim.x + threadIdx.x;
    if (n >= n_nodes) return;

    float accl[OUT_CH], accr[OUT_CH];
#pragma unroll
    for (int o = 0; o < OUT_CH; o++) { accl[o] = 0.0f; accr[o] = sb[o]; }

    const float4* hr = reinterpret_cast<const float4*>(&g_h[n * HIDDEN]);
#pragma unroll
    for (int c4 = 0; c4 < HIDDEN / 4; c4++) {
        float4 v = hr[c4];
#pragma unroll
        for (int o = 0; o < OUT_CH; o++) {
            const float* wl = &sWl[o * HIDDEN + c4 * 4];
            const float* wr = &sWr[o * HIDDEN + c4 * 4];
            accl[o] += v.x * wl[0] + v.y * wl[1] + v.z * wl[2] + v.w * wl[3];
            accr[o] += v.x * wr[0] + v.y * wr[1] + v.z * wr[2] + v.w * wr[3];
        }
    }
#pragma unroll
    for (int o = 0; o < OUT_CH; o++) {
        g_p2[n * OUT_CH + o] = accl[o];
        g_r2[n * OUT_CH + o] = accr[o];
    }
}

// Per edge: s2[dst] += p2[src]  (8 floats)
__global__ void scatter2_kernel(int n_edges, int n_nodes) {
    int e = blockIdx.x * blockDim.x + threadIdx.x;
    if (e >= n_edges) return;
    unsigned src = (unsigned)g_src[e];
    unsigned dst = (unsigned)g_dst[e];
    if (src >= (unsigned)n_nodes || dst >= (unsigned)n_nodes) return;
    const float4* p = reinterpret_cast<const float4*>(&g_p2[src * OUT_CH]);
    float* s = &g_s2[dst * OUT_CH];
#pragma unroll
    for (int q = 0; q < OUT_CH / 4; q++) {
        float4 v = p[q];
        atomicAdd(&s[q * 4 + 0], v.x);
        atomicAdd(&s[q * 4 + 1], v.y);
        atomicAdd(&s[q * 4 + 2], v.z);
        atomicAdd(&s[q * 4 + 3], v.w);
    }
}

// out = s2 / max(deg,1) + r2
__global__ void combine2_kernel(float* __restrict__ out, int n_nodes) {
    int i = blockIdx.x * blockDim.x + threadIdx.x;
    if (i >= n_nodes * OUT_CH) return;
    float d = fmaxf(g_deg[i / OUT_CH], 1.0f);
    out[i] = g_s2[i] / d + g_r2[i];
}

extern "C" void kernel_launch(void* const* d_in, const int* in_sizes, int n_in,
                              void* d_out, int out_size) {
    const float* x   = (const float*)d_in[0];
    const float* W1l = (const float*)d_in[1];
    const float* W1r = (const float*)d_in[2];
    const float* b1  = (const float*)d_in[3];
    const float* W2l = (const float*)d_in[4];
    const float* W2r = (const float*)d_in[5];
    const float* b2  = (const float*)d_in[6];
    const int*   ei  = (const int*)d_in[7];

    int n_nodes = in_sizes[0] / IN_CH;
    int n_edges = in_sizes[7] / 2;
    if (n_nodes > N_NODES_MAX) n_nodes = N_NODES_MAX;
    if (n_edges > N_EDGES_MAX) n_edges = N_EDGES_MAX;

    const int B = 256;

    detect_kernel<<<1, 32>>>(ei, in_sizes[7]);
    decode_kernel<<<(n_edges + B - 1) / B, B>>>(ei, n_edges);

    int zgrid = (n_nodes * HIDDEN + B - 1) / B;  // covers deg, s1, s2 ranges
    zero_kernel<<<zgrid, B>>>(n_nodes);

    gemm1_kernel<<<(n_nodes + B - 1) / B, B>>>(x, W1l, W1r, b1, n_nodes);
    scatter1_kernel<<<(n_edges + B - 1) / B, B>>>(n_edges, n_nodes);
    combine1_kernel<<<(n_nodes * HIDDEN + B - 1) / B, B>>>(n_nodes);

    gemm2_kernel<<<(n_nodes + B - 1) / B, B>>>(W2l, W2r, b2, n_nodes);
    scatter2_kernel<<<(n_edges + B - 1) / B, B>>>(n_edges, n_nodes);
    combine2_kernel<<<(n_nodes * OUT_CH + B - 1) / B, B>>>((float*)d_out, n_nodes);
}

// round 3
// speedup vs baseline: 1.3476x; 1.3476x over previous
#include <cuda_runtime.h>

#define N_NODES_MAX 50000
#define N_EDGES_MAX 800000
#define IN_CH 64
#define HIDDEN 16
#define OUT_CH 8

// Scratch (allocation-free rule: __device__ globals)
__device__ float g_deg[N_NODES_MAX];
__device__ float g_p1[N_NODES_MAX * HIDDEN];
__device__ float g_r1[N_NODES_MAX * HIDDEN];
__device__ float g_s1[N_NODES_MAX * HIDDEN];
__device__ float g_p2[N_NODES_MAX * OUT_CH];
__device__ float g_r2[N_NODES_MAX * OUT_CH];
__device__ float g_s2[N_NODES_MAX * OUT_CH];
__device__ int   g_src[N_EDGES_MAX];
__device__ int   g_dst[N_EDGES_MAX];
__device__ int   g_is64;

// Vectorized global reduction (sm_90+): one L2 op for 4 floats.
__device__ __forceinline__ void red_add_v4(float* addr, float4 v) {
    asm volatile("red.global.add.v4.f32 [%0], {%1, %2, %3, %4};"
                 :: "l"(addr), "f"(v.x), "f"(v.y), "f"(v.z), "f"(v.w)
                 : "memory");
}

// Fused: zero scratch accumulators + dtype detection.
// int64 little-endian with values in [0, 50000): every odd int32 word of the
// first row is 0. int32: odd words are random indices — all-zero over 512
// samples is impossible.
__global__ void init_kernel(const int* __restrict__ ei_raw, int n_words, int n_nodes) {
    int i = blockIdx.x * blockDim.x + threadIdx.x;
    if (i == 0) {
        int nz = 0;
        int lim = n_words < 1024 ? n_words : 1024;
        for (int w = 1; w < lim; w += 2) nz += (ei_raw[w] != 0);
        g_is64 = (nz == 0) ? 1 : 0;
    }
    int nh = n_nodes * HIDDEN;
    int no = n_nodes * OUT_CH;
    if (i < n_nodes) g_deg[i] = 0.0f;
    if (i < nh)      g_s1[i]  = 0.0f;
    if (i < no)      g_s2[i]  = 0.0f;
}

// Expand edge_index into int32 src/dst arrays + accumulate degree.
__global__ void decode_kernel(const int* __restrict__ ei_raw, int n_edges, int n_nodes) {
    int e = blockIdx.x * blockDim.x + threadIdx.x;
    if (e >= n_edges) return;
    int src, dst;
    if (g_is64) {
        src = ei_raw[2 * e];                  // low word of int64 src
        dst = ei_raw[2 * n_edges + 2 * e];    // low word of int64 dst
    } else {
        src = ei_raw[e];
        dst = ei_raw[n_edges + e];
    }
    g_src[e] = src;
    g_dst[e] = dst;
    if ((unsigned)dst < (unsigned)n_nodes)
        atomicAdd(&g_deg[dst], 1.0f);
}

// p1 = x @ W1l^T ; r1 = x @ W1r^T + b1
// 4 threads per node; thread quarter q computes hidden channels [4q, 4q+4).
__global__ void gemm1_kernel(const float* __restrict__ x,
                             const float* __restrict__ W1l,
                             const float* __restrict__ W1r,
                             const float* __restrict__ b1,
                             int n_nodes) {
    __shared__ float sWl[HIDDEN * IN_CH];
    __shared__ float sWr[HIDDEN * IN_CH];
    __shared__ float sb[HIDDEN];
    for (int i = threadIdx.x; i < HIDDEN * IN_CH; i += blockDim.x) {
        sWl[i] = W1l[i];
        sWr[i] = W1r[i];
    }
    if (threadIdx.x < HIDDEN) sb[threadIdx.x] = b1[threadIdx.x];
    __syncthreads();

    int idx = blockIdx.x * blockDim.x + threadIdx.x;
    int n = idx >> 2;
    int q = idx & 3;
    if (n >= n_nodes) return;
    int h0 = q * 4;

    float accl[4], accr[4];
#pragma unroll
    for (int j = 0; j < 4; j++) { accl[j] = 0.0f; accr[j] = sb[h0 + j]; }

    const float4* xr = reinterpret_cast<const float4*>(x + (size_t)n * IN_CH);
#pragma unroll
    for (int c4 = 0; c4 < IN_CH / 4; c4++) {
        float4 v = xr[c4];
#pragma unroll
        for (int j = 0; j < 4; j++) {
            const float* wl = &sWl[(h0 + j) * IN_CH + c4 * 4];
            const float* wr = &sWr[(h0 + j) * IN_CH + c4 * 4];
            accl[j] += v.x * wl[0] + v.y * wl[1] + v.z * wl[2] + v.w * wl[3];
            accr[j] += v.x * wr[0] + v.y * wr[1] + v.z * wr[2] + v.w * wr[3];
        }
    }
    float4* p1o = reinterpret_cast<float4*>(&g_p1[n * HIDDEN + h0]);
    float4* r1o = reinterpret_cast<float4*>(&g_r1[n * HIDDEN + h0]);
    *p1o = make_float4(accl[0], accl[1], accl[2], accl[3]);
    *r1o = make_float4(accr[0], accr[1], accr[2], accr[3]);
}

// Per edge: s1[dst] += p1[src]  (4 × red.v4)
__global__ void scatter1_kernel(int n_edges, int n_nodes) {
    int e = blockIdx.x * blockDim.x + threadIdx.x;
    if (e >= n_edges) return;
    unsigned src = (unsigned)g_src[e];
    unsigned dst = (unsigned)g_dst[e];
    if (src >= (unsigned)n_nodes || dst >= (unsigned)n_nodes) return;
    const float4* p = reinterpret_cast<const float4*>(&g_p1[src * HIDDEN]);
    float* s = &g_s1[dst * HIDDEN];
#pragma unroll
    for (int q = 0; q < HIDDEN / 4; q++)
        red_add_v4(&s[q * 4], p[q]);
}

// Fused: h = relu(s1/max(deg,1) + r1); p2 = h@W2l^T; r2 = h@W2r^T + b2.
// One thread per node.
__global__ void layer2_kernel(const float* __restrict__ W2l,
                              const float* __restrict__ W2r,
                              const float* __restrict__ b2,
                              int n_nodes) {
    __shared__ float sWl[OUT_CH * HIDDEN];
    __shared__ float sWr[OUT_CH * HIDDEN];
    __shared__ float sb[OUT_CH];
    for (int i = threadIdx.x; i < OUT_CH * HIDDEN; i += blockDim.x) {
        sWl[i] = W2l[i];
        sWr[i] = W2r[i];
    }
    if (threadIdx.x < OUT_CH) sb[threadIdx.x] = b2[threadIdx.x];
    __syncthreads();

    int n = blockIdx.x * blockDim.x + threadIdx.x;
    if (n >= n_nodes) return;

    float inv_d = 1.0f / fmaxf(g_deg[n], 1.0f);
    float h[HIDDEN];
    const float4* s1 = reinterpret_cast<const float4*>(&g_s1[n * HIDDEN]);
    const float4* r1 = reinterpret_cast<const float4*>(&g_r1[n * HIDDEN]);
#pragma unroll
    for (int q = 0; q < HIDDEN / 4; q++) {
        float4 sv = s1[q];
        float4 rv = r1[q];
        h[q * 4 + 0] = fmaxf(sv.x * inv_d + rv.x, 0.0f);
        h[q * 4 + 1] = fmaxf(sv.y * inv_d + rv.y, 0.0f);
        h[q * 4 + 2] = fmaxf(sv.z * inv_d + rv.z, 0.0f);
        h[q * 4 + 3] = fmaxf(sv.w * inv_d + rv.w, 0.0f);
    }

    float accl[OUT_CH], accr[OUT_CH];
#pragma unroll
    for (int o = 0; o < OUT_CH; o++) { accl[o] = 0.0f; accr[o] = sb[o]; }
#pragma unroll
    for (int c = 0; c < HIDDEN; c++) {
        float v = h[c];
#pragma unroll
        for (int o = 0; o < OUT_CH; o++) {
            accl[o] += v * sWl[o * HIDDEN + c];
            accr[o] += v * sWr[o * HIDDEN + c];
        }
    }
    float4* p2o = reinterpret_cast<float4*>(&g_p2[n * OUT_CH]);
    float4* r2o = reinterpret_cast<float4*>(&g_r2[n * OUT_CH]);
    p2o[0] = make_float4(accl[0], accl[1], accl[2], accl[3]);
    p2o[1] = make_float4(accl[4], accl[5], accl[6], accl[7]);
    r2o[0] = make_float4(accr[0], accr[1], accr[2], accr[3]);
    r2o[1] = make_float4(accr[4], accr[5], accr[6], accr[7]);
}

// Per edge: s2[dst] += p2[src]  (2 × red.v4)
__global__ void scatter2_kernel(int n_edges, int n_nodes) {
    int e = blockIdx.x * blockDim.x + threadIdx.x;
    if (e >= n_edges) return;
    unsigned src = (unsigned)g_src[e];
    unsigned dst = (unsigned)g_dst[e];
    if (src >= (unsigned)n_nodes || dst >= (unsigned)n_nodes) return;
    const float4* p = reinterpret_cast<const float4*>(&g_p2[src * OUT_CH]);
    float* s = &g_s2[dst * OUT_CH];
    red_add_v4(&s[0], p[0]);
    red_add_v4(&s[4], p[1]);
}

// out = s2 / max(deg,1) + r2
__global__ void combine2_kernel(float* __restrict__ out, int n_nodes) {
    int i = blockIdx.x * blockDim.x + threadIdx.x;
    if (i >= n_nodes * OUT_CH) return;
    float inv_d = 1.0f / fmaxf(g_deg[i / OUT_CH], 1.0f);
    out[i] = g_s2[i] * inv_d + g_r2[i];
}

extern "C" void kernel_launch(void* const* d_in, const int* in_sizes, int n_in,
                              void* d_out, int out_size) {
    const float* x   = (const float*)d_in[0];
    const float* W1l = (const float*)d_in[1];
    const float* W1r = (const float*)d_in[2];
    const float* b1  = (const float*)d_in[3];
    const float* W2l = (const float*)d_in[4];
    const float* W2r = (const float*)d_in[5];
    const float* b2  = (const float*)d_in[6];
    const int*   ei  = (const int*)d_in[7];

    int n_nodes = in_sizes[0] / IN_CH;
    int n_edges = in_sizes[7] / 2;
    if (n_nodes > N_NODES_MAX) n_nodes = N_NODES_MAX;
    if (n_edges > N_EDGES_MAX) n_edges = N_EDGES_MAX;

    const int B = 256;

    init_kernel<<<(n_nodes * HIDDEN + B - 1) / B, B>>>(ei, in_sizes[7], n_nodes);
    decode_kernel<<<(n_edges + B - 1) / B, B>>>(ei, n_edges, n_nodes);

    gemm1_kernel<<<(n_nodes * 4 + B - 1) / B, B>>>(x, W1l, W1r, b1, n_nodes);
    scatter1_kernel<<<(n_edges + B - 1) / B, B>>>(n_edges, n_nodes);

    layer2_kernel<<<(n_nodes + B - 1) / B, B>>>(W2l, W2r, b2, n_nodes);
    scatter2_kernel<<<(n_edges + B - 1) / B, B>>>(n_edges, n_nodes);
    combine2_kernel<<<(n_nodes * OUT_CH + B - 1) / B, B>>>((float*)d_out, n_nodes);
}